// round 2
// baseline (speedup 1.0000x reference)
#include <cuda_runtime.h>
#include <math.h>
#include <stdint.h>

#define B 32
#define H 480
#define W 640
#define HW (H*W)
#define NPIX (B*HW)
#define TOPK 1024
#define MAXC 32768
#define NLB 2048

// ---- scratch (device globals; no runtime allocation) ----
__device__ float g_s1m[NPIX];                      // masked score1
__device__ float g_w2m[NPIX];                      // masked warped score2
__device__ float g_gt[NPIX];                       // gaussian-smoothed gt map
__device__ unsigned long long g_cand[2ULL*B*MAXC]; // candidate keys, 2 streams
__device__ int    g_cnt[2*B];
__device__ int    g_norm;
__device__ double g_part[NLB];
__device__ float  g_gauss[25];

// ---------------------------------------------------------------- zero/init
__global__ void zero_kernel() {
    long long i = (long long)blockIdx.x * blockDim.x + threadIdx.x;
    long long stride = (long long)gridDim.x * blockDim.x;
    for (long long p = i; p < NPIX; p += stride) g_gt[p] = 0.f;
    if (i < 2*B) g_cnt[i] = 0;
    if (i == 0)  g_norm = 0;
    if (i < 25) {
        int r = (int)i / 5, c = (int)i % 5;
        // 1-D taps: exp(-(d^2)/(2*sigma^2)), sigma=2 -> exp(-d^2/8)
        double g[5]; double s = 0.0;
        #pragma unroll
        for (int t = 0; t < 5; t++) { g[t] = exp(-((double)((t-2)*(t-2))) / 8.0); s += g[t]; }
        g_gauss[i] = (float)(g[r] * g[c] / (s * s));
    }
}

// visibility value at output pixel (X,Y): bilinear sample of ones image > 0
__device__ __forceinline__ bool visval(const float* h, float X, float Y) {
    float z  = __fmaf_rn(h[6], X, __fmaf_rn(h[7], Y, h[8])) + 1e-8f;
    float px = __fmaf_rn(h[0], X, __fmaf_rn(h[1], Y, h[2])) / z;
    float py = __fmaf_rn(h[3], X, __fmaf_rn(h[4], Y, h[5])) / z;
    float x0 = floorf(px), y0 = floorf(py);
    float fx = px - x0, fy = py - y0;
    float v00 = (x0      >= 0.f && x0      <= (float)(W-1) && y0      >= 0.f && y0      <= (float)(H-1)) ? 1.f : 0.f;
    float v01 = (x0+1.f  >= 0.f && x0+1.f  <= (float)(W-1) && y0      >= 0.f && y0      <= (float)(H-1)) ? 1.f : 0.f;
    float v10 = (x0      >= 0.f && x0      <= (float)(W-1) && y0+1.f  >= 0.f && y0+1.f  <= (float)(H-1)) ? 1.f : 0.f;
    float v11 = (x0+1.f  >= 0.f && x0+1.f  <= (float)(W-1) && y0+1.f  >= 0.f && y0+1.f  <= (float)(H-1)) ? 1.f : 0.f;
    float m = v00*(1.f-fx)*(1.f-fy) + v01*fx*(1.f-fy) + v10*(1.f-fx)*fy + v11*fx*fy;
    return m > 0.f;
}

// ------------------------------------------- fused warp + erode + mask pass
__global__ void warp_kernel(const float* __restrict__ score1,
                            const float* __restrict__ score2,
                            const float* __restrict__ homo,
                            float* __restrict__ out_vis) {
    __shared__ float h[9];
    __shared__ unsigned char mt[10][34];
    int b  = blockIdx.z;
    int bx = blockIdx.x * 32, by = blockIdx.y * 8;
    int tx = threadIdx.x, ty = threadIdx.y;
    int tid = ty * 32 + tx;
    if (tid < 9) h[tid] = homo[b*9 + tid];
    __syncthreads();

    // mask tile with 1-px halo (outside image => 0, matching zero-pad erode)
    for (int j = tid; j < 340; j += 256) {
        int my = j / 34, mx = j % 34;
        int gy = by - 1 + my, gx = bx - 1 + mx;
        bool v = false;
        if (gx >= 0 && gx < W && gy >= 0 && gy < H)
            v = visval(h, (float)gx, (float)gy);
        mt[my][mx] = v ? 1 : 0;
    }
    __syncthreads();

    int x = bx + tx, y = by + ty;
    int vsum = mt[ty][tx]   & mt[ty][tx+1]   & mt[ty][tx+2]
             & mt[ty+1][tx] & mt[ty+1][tx+1] & mt[ty+1][tx+2]
             & mt[ty+2][tx] & mt[ty+2][tx+1] & mt[ty+2][tx+2];
    float vis = vsum ? 1.f : 0.f;

    // bilinear sample of score2 at warped coords of this pixel
    float X = (float)x, Y = (float)y;
    float z  = __fmaf_rn(h[6], X, __fmaf_rn(h[7], Y, h[8])) + 1e-8f;
    float px = __fmaf_rn(h[0], X, __fmaf_rn(h[1], Y, h[2])) / z;
    float py = __fmaf_rn(h[3], X, __fmaf_rn(h[4], Y, h[5])) / z;
    float x0 = floorf(px), y0 = floorf(py);
    float fx = px - x0, fy = py - y0;
    const float* img = score2 + (size_t)b * HW;

    float v00 = 0.f, v01 = 0.f, v10 = 0.f, v11 = 0.f;
    if (x0     >= 0.f && x0     <= (float)(W-1) && y0     >= 0.f && y0     <= (float)(H-1)) v00 = img[(int)y0 * W + (int)x0];
    if (x0+1.f >= 0.f && x0+1.f <= (float)(W-1) && y0     >= 0.f && y0     <= (float)(H-1)) v01 = img[(int)y0 * W + (int)(x0+1.f)];
    if (x0     >= 0.f && x0     <= (float)(W-1) && y0+1.f >= 0.f && y0+1.f <= (float)(H-1)) v10 = img[(int)(y0+1.f) * W + (int)x0];
    if (x0+1.f >= 0.f && x0+1.f <= (float)(W-1) && y0+1.f >= 0.f && y0+1.f <= (float)(H-1)) v11 = img[(int)(y0+1.f) * W + (int)(x0+1.f)];
    float w2 = v00*(1.f-fx)*(1.f-fy) + v01*fx*(1.f-fy) + v10*(1.f-fx)*fy + v11*fx*fy;

    size_t i = (size_t)b * HW + (size_t)y * W + x;
    out_vis[i] = vis;
    g_s1m[i] = score1[i] * vis;
    g_w2m[i] = w2 * vis;

    int c = __syncthreads_count(vsum);
    if (tid == 0) atomicAdd(&g_norm, c);
}

// --------------------------------------------------------- 5x5 NMS -> lists
__global__ void nms_kernel() {
    __shared__ float t[12][36];
    int zz = blockIdx.z;
    int s = zz / B, b = zz % B;
    const float* src = ((s == 0) ? g_s1m : g_w2m) + (size_t)b * HW;
    int bx = blockIdx.x * 32, by = blockIdx.y * 8;
    int tx = threadIdx.x, ty = threadIdx.y, tid = ty * 32 + tx;

    for (int j = tid; j < 12*36; j += 256) {
        int r = j / 36, c = j % 36;
        int gy = by - 2 + r, gx = bx - 2 + c;
        t[r][c] = (gx >= 0 && gx < W && gy >= 0 && gy < H) ? src[gy*W + gx] : -INFINITY;
    }
    __syncthreads();

    float sv = t[ty+2][tx+2];
    if (sv > 0.3f) {
        float mx = -INFINITY;
        #pragma unroll
        for (int dy = 0; dy < 5; dy++)
            #pragma unroll
            for (int dx = 0; dx < 5; dx++)
                mx = fmaxf(mx, t[ty+dy][tx+dx]);
        if (sv == mx) {
            int idx = (by+ty)*W + (bx+tx);
            unsigned long long key =
                ((unsigned long long)__float_as_uint(sv) << 32) | (unsigned)(~idx);
            int p = atomicAdd(&g_cnt[s*B + b], 1);
            if (p < MAXC) g_cand[(size_t)(s*B + b)*MAXC + p] = key;
        }
    }
}

// ------------------------------------ top-1024 select + sort + kp/gt output
__global__ void __launch_bounds__(1024) select_kernel(float* __restrict__ out) {
    __shared__ unsigned long long sel[TOPK];
    __shared__ unsigned int hist[256];
    __shared__ unsigned long long sh_pref;
    __shared__ unsigned int sh_rem;
    __shared__ int sh_cnt;

    int b = blockIdx.x, s = blockIdx.y;
    int li = s*B + b;
    int n = g_cnt[li]; if (n > MAXC) n = MAXC;
    const unsigned long long* keys = g_cand + (size_t)li * MAXC;
    int tid = threadIdx.x;

    sel[tid] = 0ULL;
    if (tid == 0) { sh_pref = 0ULL; sh_rem = TOPK; sh_cnt = 0; }
    __syncthreads();

    if (n > TOPK) {
        // radix-select the exact 1024th-largest key (keys unique via idx bits)
        for (int shift = 56; shift >= 0; shift -= 8) {
            if (tid < 256) hist[tid] = 0;
            __syncthreads();
            unsigned long long pref  = sh_pref;
            unsigned long long pmask = (shift == 56) ? 0ULL : (~0ULL << (shift + 8));
            for (int i = tid; i < n; i += 1024) {
                unsigned long long k = keys[i];
                if ((k & pmask) == pref)
                    atomicAdd(&hist[(unsigned)(k >> shift) & 255u], 1u);
            }
            __syncthreads();
            if (tid == 0) {
                unsigned rem = sh_rem;
                for (int bin = 255; bin >= 0; bin--) {
                    unsigned c = hist[bin];
                    if (c < rem) rem -= c;
                    else { sh_pref = pref | ((unsigned long long)bin << shift); break; }
                }
                sh_rem = rem;
            }
            __syncthreads();
        }
        unsigned long long kth = sh_pref;
        for (int i = tid; i < n; i += 1024) {
            unsigned long long k = keys[i];
            if (k >= kth) { int p = atomicAdd(&sh_cnt, 1); if (p < TOPK) sel[p] = k; }
        }
    } else {
        if (tid < n) sel[tid] = keys[tid];
    }
    __syncthreads();

    // bitonic sort, descending (padding zeros sink to the end)
    for (unsigned k = 2; k <= TOPK; k <<= 1) {
        for (unsigned j = k >> 1; j > 0; j >>= 1) {
            unsigned i = (unsigned)tid, ixj = i ^ j;
            if (ixj > i) {
                unsigned long long a = sel[i], c = sel[ixj];
                bool up = ((i & k) == 0);
                bool sw = up ? (a < c) : (a > c);
                if (sw) { sel[i] = c; sel[ixj] = a; }
            }
            __syncthreads();
        }
    }

    int m = (n < TOPK) ? n : TOPK;
    if (s == 0) {
        // kp1 output: (y, x) as floats
        if (tid < m) {
            unsigned idx = ~(unsigned)(sel[tid] & 0xFFFFFFFFu);
            out[1 + ((size_t)b*TOPK + tid)*2]     = (float)(idx / W);
            out[1 + ((size_t)b*TOPK + tid)*2 + 1] = (float)(idx % W);
        }
        __syncthreads();
        // jax top_k pad semantics: remaining slots = lowest zero-valued indices
        if (tid == 0 && m < TOPK) {
            int cursor = 0;
            for (int j = m; j < TOPK; j++) {
                for (;;) {
                    bool isc = false;
                    for (int t = 0; t < m; t++) {
                        unsigned idx = ~(unsigned)(sel[t] & 0xFFFFFFFFu);
                        if ((int)idx == cursor) { isc = true; break; }
                    }
                    if (!isc) break;
                    cursor++;
                }
                out[1 + ((size_t)b*TOPK + j)*2]     = (float)(cursor / W);
                out[1 + ((size_t)b*TOPK + j)*2 + 1] = (float)(cursor % W);
                cursor++;
            }
        }
    } else {
        // scatter 5x5 gaussian from each selected gt keypoint
        if (tid < m) {
            unsigned long long kk = sel[tid];
            float v = __uint_as_float((unsigned)(kk >> 32));
            unsigned idx = ~(unsigned)(kk & 0xFFFFFFFFu);
            int y = (int)(idx / W), x = (int)(idx % W);
            float* gtb = g_gt + (size_t)b * HW;
            #pragma unroll
            for (int dy = -2; dy <= 2; dy++) {
                int yy = y + dy; if (yy < 0 || yy >= H) continue;
                #pragma unroll
                for (int dx = -2; dx <= 2; dx++) {
                    int xx = x + dx; if (xx < 0 || xx >= W) continue;
                    atomicAdd(&gtb[yy*W + xx], v * g_gauss[(dy+2)*5 + (dx+2)]);
                }
            }
        }
    }
}

// -------------------------------------------------------------- loss reduce
__global__ void loss_kernel() {
    long long i0 = (long long)blockIdx.x * blockDim.x + threadIdx.x;
    long long stride = (long long)gridDim.x * blockDim.x;
    double acc = 0.0;
    for (long long i = i0; i < NPIX; i += stride) {
        float d = g_s1m[i] - g_gt[i];
        acc += (double)(d * d);
    }
    __shared__ double sm[256];
    sm[threadIdx.x] = acc; __syncthreads();
    for (int o = 128; o > 0; o >>= 1) {
        if (threadIdx.x < o) sm[threadIdx.x] += sm[threadIdx.x + o];
        __syncthreads();
    }
    if (threadIdx.x == 0) g_part[blockIdx.x] = sm[0];
}

__global__ void final_kernel(float* __restrict__ out) {
    __shared__ double sm[256];
    double a = 0.0;
    for (int j = 0; j < NLB/256; j++) a += g_part[threadIdx.x * (NLB/256) + j];
    sm[threadIdx.x] = a; __syncthreads();
    for (int o = 128; o > 0; o >>= 1) {
        if (threadIdx.x < o) sm[threadIdx.x] += sm[threadIdx.x + o];
        __syncthreads();
    }
    if (threadIdx.x == 0) out[0] = (float)(sm[0] / (double)g_norm);
}

// ------------------------------------------------------------------- launch
extern "C" void kernel_launch(void* const* d_in, const int* in_sizes, int n_in,
                              void* d_out, int out_size) {
    // identify homo (B*9 elems); scores assumed in declaration order otherwise
    int hi = 2;
    if (in_sizes[0] == B*9) hi = 0;
    else if (in_sizes[1] == B*9) hi = 1;
    int s1i = (hi == 0) ? 1 : 0;
    int s2i = 3 - hi - s1i;

    const float* score1 = (const float*)d_in[s1i];
    const float* score2 = (const float*)d_in[s2i];
    const float* homo   = (const float*)d_in[hi];
    float* out = (float*)d_out;
    float* out_vis = out + 1 + (size_t)B * TOPK * 2;

    dim3 blk(32, 8);
    zero_kernel<<<4096, 256>>>();
    warp_kernel<<<dim3(W/32, H/8, B), blk>>>(score1, score2, homo, out_vis);
    nms_kernel<<<dim3(W/32, H/8, 2*B), blk>>>();
    select_kernel<<<dim3(B, 2), 1024>>>(out);
    loss_kernel<<<NLB, 256>>>();
    final_kernel<<<1, 256>>>(out);
}